// round 14
// baseline (speedup 1.0000x reference)
#include <cuda_runtime.h>
#include <cuda_bf16.h>

#define NDIM 128
#define EDIM 32
#define MAX_N 100000

// Scatter accumulator. Zero-initialized at module load; node_kernel re-zeroes
// every element it consumes, restoring the invariant for the next graph replay.
__device__ float g_h[(size_t)MAX_N * NDIM];

// ---------------- packed f32x2 helpers ----------------
__device__ __forceinline__ unsigned long long pack2(float x, float y) {
    unsigned long long r;
    asm("mov.b64 %0, {%1, %2};" : "=l"(r) : "f"(x), "f"(y));
    return r;
}
__device__ __forceinline__ void unpack2(unsigned long long v, float& x, float& y) {
    asm("mov.b64 {%0, %1}, %2;" : "=f"(x), "=f"(y) : "l"(v));
}
__device__ __forceinline__ void ffma2(unsigned long long& d, unsigned long long a, unsigned long long b) {
    asm("fma.rn.f32x2 %0, %1, %2, %0;" : "+l"(d) : "l"(a), "l"(b));
}

// ---------------- kernel 1: edge MLP + gather + scatter ----------------
// msg[e] = edge_attr[e] @ We + be + x[j[e]];  red.add.v4 -> g_h[i[e]]
// 256 threads = 8 warps, 16 edges per warp -> 128 edges per block.
#define EPW 16
__global__ __launch_bounds__(256) void edge_kernel(
    const float* __restrict__ x,
    const int* __restrict__ ei,         // [2, E] int32: ei[e]=dst i, ei[nE+e]=src j
    const float* __restrict__ ea,       // [E, 32]
    const float* __restrict__ We,       // [32, 128]
    const float* __restrict__ be,       // [128]
    int nE, int nN)
{
    __shared__ float sWe[EDIM * NDIM];          // 16 KB
    __shared__ float sea[8][EPW][EDIM];         // 16 KB

    int tid = threadIdx.x;
    for (int i = tid; i < EDIM * NDIM; i += blockDim.x) sWe[i] = We[i];

    int warp = tid >> 5, lane = tid & 31;
    int ebase = blockIdx.x * (8 * EPW) + warp * EPW;

    // stage 16 edges' attrs: lane loads attr[lane] of each edge (coalesced 128B)
    #pragma unroll
    for (int nn = 0; nn < EPW; nn++) {
        int e = ebase + nn;
        sea[warp][nn][lane] = (e < nE) ? __ldg(&ea[(size_t)e * EDIM + lane]) : 0.0f;
    }
    // indices: lanes 0..15 load (i, j) of edge ebase+lane; clamp into [0,nN)
    int iv = 0, jv = 0;
    if (lane < EPW) {
        int e = ebase + lane;
        if (e < nE) {
            iv = min(max(__ldg(&ei[e]), 0), nN - 1);
            jv = min(max(__ldg(&ei[nE + e]), 0), nN - 1);
        }
    }
    __syncthreads();

    // register-blocked GEMM: lane owns cols [lane*4, lane*4+4)
    unsigned long long acc[EPW][2];
    #pragma unroll
    for (int nn = 0; nn < EPW; nn++) { acc[nn][0] = 0ULL; acc[nn][1] = 0ULL; }

    const ulonglong2* We2 = (const ulonglong2*)sWe;
    #pragma unroll
    for (int dq = 0; dq < EDIM / 4; dq++) {
        ulonglong2 w[4];
        #pragma unroll
        for (int k = 0; k < 4; k++)
            w[k] = We2[(dq * 4 + k) * 32 + lane];
        #pragma unroll
        for (int nn = 0; nn < EPW; nn++) {
            float4 a = ((const float4*)sea[warp][nn])[dq];
            unsigned long long aa;
            aa = pack2(a.x, a.x); ffma2(acc[nn][0], aa, w[0].x); ffma2(acc[nn][1], aa, w[0].y);
            aa = pack2(a.y, a.y); ffma2(acc[nn][0], aa, w[1].x); ffma2(acc[nn][1], aa, w[1].y);
            aa = pack2(a.z, a.z); ffma2(acc[nn][0], aa, w[2].x); ffma2(acc[nn][1], aa, w[2].y);
            aa = pack2(a.w, a.w); ffma2(acc[nn][0], aa, w[3].x); ffma2(acc[nn][1], aa, w[3].y);
        }
    }

    float4 b = __ldg(&((const float4*)be)[lane]);
    #pragma unroll
    for (int nn = 0; nn < EPW; nn++) {
        int e = ebase + nn;
        if (e < nE) {
            int jn  = __shfl_sync(0xffffffffu, jv, nn);
            int in_ = __shfl_sync(0xffffffffu, iv, nn);
            float4 xv = __ldg(&((const float4*)x)[(size_t)jn * 32 + lane]);
            float m0, m1, m2, m3;
            unpack2(acc[nn][0], m0, m1);
            unpack2(acc[nn][1], m2, m3);
            m0 += b.x + xv.x;
            m1 += b.y + xv.y;
            m2 += b.z + xv.z;
            m3 += b.w + xv.w;
            float* dst = g_h + (size_t)in_ * NDIM + lane * 4;
            asm volatile("red.global.add.v4.f32 [%0], {%1,%2,%3,%4};"
                         :: "l"(dst), "f"(m0), "f"(m1), "f"(m2), "f"(m3)
                         : "memory");
        }
    }
}

// ---------------- kernel 2: node MLP + LayerNorm ----------------
// h = (1+eps)*x + g_h;  out = LN(relu(h@W1+b1)@W2+b2);  g_h := 0 (restore)
// 384 threads = 12 warps, 16 nodes/warp -> 192 nodes per block.
// smem: W1 (64KB) + W2 (64KB) + 12 warps * 16x128 staging (96KB) = 224KB
#define NWARPS 12
#define NPW 16
__global__ __launch_bounds__(384) void node_kernel(
    const float* __restrict__ x, const float* __restrict__ eps,
    const float* __restrict__ W1, const float* __restrict__ b1,
    const float* __restrict__ W2, const float* __restrict__ b2,
    const float* __restrict__ gamma, const float* __restrict__ beta,
    float* __restrict__ out, int n)
{
    extern __shared__ float sm[];
    float* sW1 = sm;                       // 16384 floats
    float* sW2 = sm + NDIM * NDIM;         // 16384 floats
    float* sstage = sm + 2 * NDIM * NDIM;  // 12 warps * 16 * 128 floats

    int tid = threadIdx.x, warp = tid >> 5, lane = tid & 31;
    for (int i = tid; i < NDIM * NDIM; i += blockDim.x) {
        sW1[i] = W1[i];
        sW2[i] = W2[i];
    }
    float s1e = 1.0f + __ldg(eps);
    float4 b1v = __ldg(&((const float4*)b1)[lane]);
    float4 b2v = __ldg(&((const float4*)b2)[lane]);
    float4 gv  = __ldg(&((const float4*)gamma)[lane]);
    float4 bv  = __ldg(&((const float4*)beta)[lane]);
    __syncthreads();

    float* st = sstage + warp * (NPW * NDIM);
    const float4* x4 = (const float4*)x;
    float4* gh4 = (float4*)g_h;
    int nbase = blockIdx.x * (NWARPS * NPW) + warp * NPW;

    // stage h = (1+eps)*x + agg; restore agg to zero for next replay
    #pragma unroll
    for (int nn = 0; nn < NPW; nn++) {
        int node = nbase + nn;
        float4 v = make_float4(0.f, 0.f, 0.f, 0.f);
        if (node < n) {
            size_t idx = (size_t)node * 32 + lane;
            float4 xv = x4[idx];
            float4 av = gh4[idx];
            v.x = s1e * xv.x + av.x;
            v.y = s1e * xv.y + av.y;
            v.z = s1e * xv.z + av.z;
            v.w = s1e * xv.w + av.w;
            gh4[idx] = make_float4(0.f, 0.f, 0.f, 0.f);
        }
        ((float4*)st)[nn * 32 + lane] = v;
    }
    __syncwarp();

    unsigned long long acc[NPW][2];
    const ulonglong2* W1u = (const ulonglong2*)sW1;
    const ulonglong2* W2u = (const ulonglong2*)sW2;

    // ---- layer 1: t = relu(h @ W1 + b1) ----
    #pragma unroll
    for (int nn = 0; nn < NPW; nn++) { acc[nn][0] = 0ULL; acc[nn][1] = 0ULL; }

    #pragma unroll 2
    for (int dq = 0; dq < NDIM / 4; dq++) {
        ulonglong2 w[4];
        #pragma unroll
        for (int k = 0; k < 4; k++)
            w[k] = W1u[(dq * 4 + k) * 32 + lane];
        #pragma unroll
        for (int nn = 0; nn < NPW; nn++) {
            float4 a = ((const float4*)st)[nn * 32 + dq];
            unsigned long long aa;
            aa = pack2(a.x, a.x); ffma2(acc[nn][0], aa, w[0].x); ffma2(acc[nn][1], aa, w[0].y);
            aa = pack2(a.y, a.y); ffma2(acc[nn][0], aa, w[1].x); ffma2(acc[nn][1], aa, w[1].y);
            aa = pack2(a.z, a.z); ffma2(acc[nn][0], aa, w[2].x); ffma2(acc[nn][1], aa, w[2].y);
            aa = pack2(a.w, a.w); ffma2(acc[nn][0], aa, w[3].x); ffma2(acc[nn][1], aa, w[3].y);
        }
    }

    __syncwarp();  // all lanes done reading st before overwrite
    #pragma unroll
    for (int nn = 0; nn < NPW; nn++) {
        float t0, t1, t2, t3;
        unpack2(acc[nn][0], t0, t1);
        unpack2(acc[nn][1], t2, t3);
        t0 = fmaxf(t0 + b1v.x, 0.f);
        t1 = fmaxf(t1 + b1v.y, 0.f);
        t2 = fmaxf(t2 + b1v.z, 0.f);
        t3 = fmaxf(t3 + b1v.w, 0.f);
        ((float4*)st)[nn * 32 + lane] = make_float4(t0, t1, t2, t3);
    }
    __syncwarp();

    // ---- layer 2: o = t @ W2 + b2 ----
    #pragma unroll
    for (int nn = 0; nn < NPW; nn++) { acc[nn][0] = 0ULL; acc[nn][1] = 0ULL; }

    #pragma unroll 2
    for (int dq = 0; dq < NDIM / 4; dq++) {
        ulonglong2 w[4];
        #pragma unroll
        for (int k = 0; k < 4; k++)
            w[k] = W2u[(dq * 4 + k) * 32 + lane];
        #pragma unroll
        for (int nn = 0; nn < NPW; nn++) {
            float4 a = ((const float4*)st)[nn * 32 + dq];
            unsigned long long aa;
            aa = pack2(a.x, a.x); ffma2(acc[nn][0], aa, w[0].x); ffma2(acc[nn][1], aa, w[0].y);
            aa = pack2(a.y, a.y); ffma2(acc[nn][0], aa, w[1].x); ffma2(acc[nn][1], aa, w[1].y);
            aa = pack2(a.z, a.z); ffma2(acc[nn][0], aa, w[2].x); ffma2(acc[nn][1], aa, w[2].y);
            aa = pack2(a.w, a.w); ffma2(acc[nn][0], aa, w[3].x); ffma2(acc[nn][1], aa, w[3].y);
        }
    }

    // ---- LayerNorm per node ----
    #pragma unroll
    for (int nn = 0; nn < NPW; nn++) {
        int node = nbase + nn;
        float o0, o1, o2, o3;
        unpack2(acc[nn][0], o0, o1);
        unpack2(acc[nn][1], o2, o3);
        o0 += b2v.x; o1 += b2v.y; o2 += b2v.z; o3 += b2v.w;
        float s = o0 + o1 + o2 + o3;
        float s2 = o0 * o0 + o1 * o1 + o2 * o2 + o3 * o3;
        #pragma unroll
        for (int off = 16; off > 0; off >>= 1) {
            s  += __shfl_xor_sync(0xffffffffu, s, off);
            s2 += __shfl_xor_sync(0xffffffffu, s2, off);
        }
        float mean = s * (1.0f / NDIM);
        float var = s2 * (1.0f / NDIM) - mean * mean;
        float rstd = rsqrtf(var + 1e-5f);
        float4 o;
        o.x = (o0 - mean) * rstd * gv.x + bv.x;
        o.y = (o1 - mean) * rstd * gv.y + bv.y;
        o.z = (o2 - mean) * rstd * gv.z + bv.z;
        o.w = (o3 - mean) * rstd * gv.w + bv.w;
        if (node < n) ((float4*)out)[(size_t)node * 32 + lane] = o;
    }
}

// ---------------- launch ----------------
extern "C" void kernel_launch(void* const* d_in, const int* in_sizes, int n_in,
                              void* d_out, int out_size) {
    const float* x      = (const float*)d_in[0];
    const int*   ei     = (const int*)d_in[1];     // int32
    const float* ea     = (const float*)d_in[2];
    const float* We     = (const float*)d_in[3];
    const float* be     = (const float*)d_in[4];
    const float* W1     = (const float*)d_in[5];
    const float* b1     = (const float*)d_in[6];
    const float* W2     = (const float*)d_in[7];
    const float* b2     = (const float*)d_in[8];
    const float* eps    = (const float*)d_in[9];
    const float* gamma  = (const float*)d_in[10];
    const float* beta   = (const float*)d_in[11];
    float* out = (float*)d_out;

    int n = in_sizes[0] / NDIM;        // 100000
    int nE = in_sizes[2] / EDIM;       // 600000

    // kernel 1: edges (g_h starts all-zero: zero-init at load, restored by node_kernel)
    {
        int edges_per_block = 8 * EPW;  // 128
        int blocks = (nE + edges_per_block - 1) / edges_per_block;
        edge_kernel<<<blocks, 256>>>(x, ei, ea, We, be, nE, n);
    }
    // kernel 2: node MLP + LN (one block per 192-node tile)
    {
        int smem = (2 * NDIM * NDIM + NWARPS * NPW * NDIM) * sizeof(float); // 224KB
        cudaFuncSetAttribute(node_kernel,
                             cudaFuncAttributeMaxDynamicSharedMemorySize, smem);
        int nodes_per_block = NWARPS * NPW; // 192
        int blocks = (n + nodes_per_block - 1) / nodes_per_block;
        node_kernel<<<blocks, 384, smem>>>(x, eps, W1, b1, W2, b2, gamma, beta,
                                           out, n);
    }
}

// round 16
// speedup vs baseline: 1.7600x; 1.7600x over previous
#include <cuda_runtime.h>
#include <cuda_bf16.h>

#define NDIM 128
#define EDIM 32
#define MAX_N 100000

// Scratch aggregation buffer: h = (1+eps)*x + scatter_sum(msg)
__device__ float g_h[(size_t)MAX_N * NDIM];

// ---------------- packed f32x2 helpers ----------------
__device__ __forceinline__ unsigned long long pack2(float x, float y) {
    unsigned long long r;
    asm("mov.b64 %0, {%1, %2};" : "=l"(r) : "f"(x), "f"(y));
    return r;
}
__device__ __forceinline__ void unpack2(unsigned long long v, float& x, float& y) {
    asm("mov.b64 {%0, %1}, %2;" : "=f"(x), "=f"(y) : "l"(v));
}
__device__ __forceinline__ void ffma2(unsigned long long& d, unsigned long long a, unsigned long long b) {
    asm("fma.rn.f32x2 %0, %1, %2, %0;" : "+l"(d) : "l"(a), "l"(b));
}

// ---------------- kernel 1: h = (1+eps) * x ----------------
__global__ void init_h_kernel(const float* __restrict__ x,
                              const float* __restrict__ eps, int n) {
    float s = 1.0f + __ldg(eps);
    int total4 = n * (NDIM / 4);
    const float4* x4 = (const float4*)x;
    float4* h4 = (float4*)g_h;
    for (int i = blockIdx.x * blockDim.x + threadIdx.x; i < total4;
         i += gridDim.x * blockDim.x) {
        float4 v = x4[i];
        v.x *= s; v.y *= s; v.z *= s; v.w *= s;
        h4[i] = v;
    }
}

// ---------------- kernel 2: edge MLP + gather + scatter (R7 proven) ----------
// msg[e] = edge_attr[e] @ We + be + x[j[e]];  red.add.v4 -> g_h[i[e]]
// 256 threads = 8 warps, 8 edges per warp -> 64 edges per block.
#define EPW 8
__global__ __launch_bounds__(256) void edge_kernel(
    const float* __restrict__ x,
    const int* __restrict__ ei,         // [2, E] int32: ei[e]=dst i, ei[nE+e]=src j
    const float* __restrict__ ea,       // [E, 32]
    const float* __restrict__ We,       // [32, 128]
    const float* __restrict__ be,       // [128]
    int nE, int nN)
{
    __shared__ float sWe[EDIM * NDIM];      // 16 KB
    __shared__ float sea[8][EPW][EDIM];     // 8 KB

    int tid = threadIdx.x;
    for (int i = tid; i < EDIM * NDIM; i += blockDim.x) sWe[i] = We[i];

    int warp = tid >> 5, lane = tid & 31;
    int ebase = blockIdx.x * (8 * EPW) + warp * EPW;

    #pragma unroll
    for (int nn = 0; nn < EPW; nn++) {
        int e = ebase + nn;
        sea[warp][nn][lane] = (e < nE) ? __ldg(&ea[(size_t)e * EDIM + lane]) : 0.0f;
    }
    int iv = 0, jv = 0;
    if (lane < EPW) {
        int e = ebase + lane;
        if (e < nE) {
            iv = min(max(__ldg(&ei[e]), 0), nN - 1);
            jv = min(max(__ldg(&ei[nE + e]), 0), nN - 1);
        }
    }
    __syncthreads();

    unsigned long long acc[EPW][2];
    #pragma unroll
    for (int nn = 0; nn < EPW; nn++) { acc[nn][0] = 0ULL; acc[nn][1] = 0ULL; }

    const float4* We4 = (const float4*)sWe;
    #pragma unroll
    for (int dq = 0; dq < EDIM / 4; dq++) {
        float4 av[EPW];
        #pragma unroll
        for (int nn = 0; nn < EPW; nn++)
            av[nn] = ((const float4*)sea[warp][nn])[dq];
        #pragma unroll
        for (int k = 0; k < 4; k++) {
            int d = dq * 4 + k;
            float4 w = We4[d * 32 + lane];
            unsigned long long w01 = pack2(w.x, w.y);
            unsigned long long w23 = pack2(w.z, w.w);
            #pragma unroll
            for (int nn = 0; nn < EPW; nn++) {
                float a = (k == 0) ? av[nn].x : (k == 1) ? av[nn].y
                        : (k == 2) ? av[nn].z : av[nn].w;
                unsigned long long aa = pack2(a, a);
                ffma2(acc[nn][0], aa, w01);
                ffma2(acc[nn][1], aa, w23);
            }
        }
    }

    float4 b = __ldg(&((const float4*)be)[lane]);
    #pragma unroll
    for (int nn = 0; nn < EPW; nn++) {
        int e = ebase + nn;
        if (e < nE) {
            int jn  = __shfl_sync(0xffffffffu, jv, nn);
            int in_ = __shfl_sync(0xffffffffu, iv, nn);
            float4 xv = __ldg(&((const float4*)x)[(size_t)jn * 32 + lane]);
            float m0, m1, m2, m3;
            unpack2(acc[nn][0], m0, m1);
            unpack2(acc[nn][1], m2, m3);
            m0 += b.x + xv.x;
            m1 += b.y + xv.y;
            m2 += b.z + xv.z;
            m3 += b.w + xv.w;
            float* dst = g_h + (size_t)in_ * NDIM + lane * 4;
            asm volatile("red.global.add.v4.f32 [%0], {%1,%2,%3,%4};"
                         :: "l"(dst), "f"(m0), "f"(m1), "f"(m2), "f"(m3)
                         : "memory");
        }
    }
}

// ---------------- kernel 3: node MLP + LayerNorm ----------------
// out = LN(relu(h@W1+b1)@W2+b2)
// 1024 threads = 32 warps, 4 nodes/warp -> 128 nodes/block.
// smem: W1 (64KB) + W2 (64KB) + 32 warps * 4x128 staging (64KB) = 192KB
#define NWARPS 32
#define NPW 4
__global__ __launch_bounds__(1024) void node_kernel(
    const float* __restrict__ W1, const float* __restrict__ b1,
    const float* __restrict__ W2, const float* __restrict__ b2,
    const float* __restrict__ gamma, const float* __restrict__ beta,
    float* __restrict__ out, int n)
{
    extern __shared__ float sm[];
    float* sW1 = sm;                       // 16384 floats
    float* sW2 = sm + NDIM * NDIM;         // 16384 floats
    float* sstage = sm + 2 * NDIM * NDIM;  // 32 warps * 4 * 128 floats

    int tid = threadIdx.x, warp = tid >> 5, lane = tid & 31;
    for (int i = tid; i < NDIM * NDIM; i += blockDim.x) {
        sW1[i] = W1[i];
        sW2[i] = W2[i];
    }
    __syncthreads();

    float* st = sstage + warp * (NPW * NDIM);
    int nbase = blockIdx.x * (NWARPS * NPW) + warp * NPW;

    // stage h rows (coalesced float4 per node)
    #pragma unroll
    for (int nn = 0; nn < NPW; nn++) {
        int node = nbase + nn;
        float4 v = make_float4(0.f, 0.f, 0.f, 0.f);
        if (node < n) v = ((const float4*)g_h)[(size_t)node * 32 + lane];
        ((float4*)st)[nn * 32 + lane] = v;
    }
    __syncwarp();

    // ---- layer 1: t = relu(h @ W1 + b1) ----
    unsigned long long acc[NPW][2];
    #pragma unroll
    for (int nn = 0; nn < NPW; nn++) { acc[nn][0] = 0ULL; acc[nn][1] = 0ULL; }

    const float4* W14 = (const float4*)sW1;
    #pragma unroll 4
    for (int dq = 0; dq < NDIM / 4; dq++) {
        float4 av[NPW];
        #pragma unroll
        for (int nn = 0; nn < NPW; nn++)
            av[nn] = ((const float4*)st)[nn * 32 + dq];
        #pragma unroll
        for (int k = 0; k < 4; k++) {
            float4 w = W14[(dq * 4 + k) * 32 + lane];
            unsigned long long w01 = pack2(w.x, w.y);
            unsigned long long w23 = pack2(w.z, w.w);
            #pragma unroll
            for (int nn = 0; nn < NPW; nn++) {
                float hv = (k == 0) ? av[nn].x : (k == 1) ? av[nn].y
                         : (k == 2) ? av[nn].z : av[nn].w;
                unsigned long long aa = pack2(hv, hv);
                ffma2(acc[nn][0], aa, w01);
                ffma2(acc[nn][1], aa, w23);
            }
        }
    }

    float4 b1v = __ldg(&((const float4*)b1)[lane]);
    __syncwarp();  // all lanes done reading st before overwrite
    #pragma unroll
    for (int nn = 0; nn < NPW; nn++) {
        float t0, t1, t2, t3;
        unpack2(acc[nn][0], t0, t1);
        unpack2(acc[nn][1], t2, t3);
        t0 = fmaxf(t0 + b1v.x, 0.f);
        t1 = fmaxf(t1 + b1v.y, 0.f);
        t2 = fmaxf(t2 + b1v.z, 0.f);
        t3 = fmaxf(t3 + b1v.w, 0.f);
        ((float4*)st)[nn * 32 + lane] = make_float4(t0, t1, t2, t3);
    }
    __syncwarp();

    // ---- layer 2: o = t @ W2 + b2 ----
    #pragma unroll
    for (int nn = 0; nn < NPW; nn++) { acc[nn][0] = 0ULL; acc[nn][1] = 0ULL; }
    const float4* W24 = (const float4*)sW2;
    #pragma unroll 4
    for (int dq = 0; dq < NDIM / 4; dq++) {
        float4 av[NPW];
        #pragma unroll
        for (int nn = 0; nn < NPW; nn++)
            av[nn] = ((const float4*)st)[nn * 32 + dq];
        #pragma unroll
        for (int k = 0; k < 4; k++) {
            float4 w = W24[(dq * 4 + k) * 32 + lane];
            unsigned long long w01 = pack2(w.x, w.y);
            unsigned long long w23 = pack2(w.z, w.w);
            #pragma unroll
            for (int nn = 0; nn < NPW; nn++) {
                float tv = (k == 0) ? av[nn].x : (k == 1) ? av[nn].y
                         : (k == 2) ? av[nn].z : av[nn].w;
                unsigned long long aa = pack2(tv, tv);
                ffma2(acc[nn][0], aa, w01);
                ffma2(acc[nn][1], aa, w23);
            }
        }
    }

    float4 b2v = __ldg(&((const float4*)b2)[lane]);
    float4 gv  = __ldg(&((const float4*)gamma)[lane]);
    float4 bv  = __ldg(&((const float4*)beta)[lane]);

    // ---- LayerNorm per node ----
    #pragma unroll
    for (int nn = 0; nn < NPW; nn++) {
        int node = nbase + nn;
        float o0, o1, o2, o3;
        unpack2(acc[nn][0], o0, o1);
        unpack2(acc[nn][1], o2, o3);
        o0 += b2v.x; o1 += b2v.y; o2 += b2v.z; o3 += b2v.w;
        float s = o0 + o1 + o2 + o3;
        float s2 = o0 * o0 + o1 * o1 + o2 * o2 + o3 * o3;
        #pragma unroll
        for (int off = 16; off > 0; off >>= 1) {
            s  += __shfl_xor_sync(0xffffffffu, s, off);
            s2 += __shfl_xor_sync(0xffffffffu, s2, off);
        }
        float mean = s * (1.0f / NDIM);
        float var = s2 * (1.0f / NDIM) - mean * mean;
        float rstd = rsqrtf(var + 1e-5f);
        float4 o;
        o.x = (o0 - mean) * rstd * gv.x + bv.x;
        o.y = (o1 - mean) * rstd * gv.y + bv.y;
        o.z = (o2 - mean) * rstd * gv.z + bv.z;
        o.w = (o3 - mean) * rstd * gv.w + bv.w;
        if (node < n) ((float4*)out)[(size_t)node * 32 + lane] = o;
    }
}

// ---------------- launch ----------------
extern "C" void kernel_launch(void* const* d_in, const int* in_sizes, int n_in,
                              void* d_out, int out_size) {
    const float* x      = (const float*)d_in[0];
    const int*   ei     = (const int*)d_in[1];     // int32
    const float* ea     = (const float*)d_in[2];
    const float* We     = (const float*)d_in[3];
    const float* be     = (const float*)d_in[4];
    const float* W1     = (const float*)d_in[5];
    const float* b1     = (const float*)d_in[6];
    const float* W2     = (const float*)d_in[7];
    const float* b2     = (const float*)d_in[8];
    const float* eps    = (const float*)d_in[9];
    const float* gamma  = (const float*)d_in[10];
    const float* beta   = (const float*)d_in[11];
    float* out = (float*)d_out;

    int n = in_sizes[0] / NDIM;        // 100000
    int nE = in_sizes[2] / EDIM;       // 600000

    // kernel 1: init h = (1+eps)*x
    {
        int total4 = n * (NDIM / 4);
        int blocks = (total4 + 255) / 256;
        if (blocks > 4096) blocks = 4096;
        init_h_kernel<<<blocks, 256>>>(x, eps, n);
    }
    // kernel 2: edges
    {
        int edges_per_block = 8 * EPW;  // 64
        int blocks = (nE + edges_per_block - 1) / edges_per_block;
        edge_kernel<<<blocks, 256>>>(x, ei, ea, We, be, nE, n);
    }
    // kernel 3: node MLP + LN (one block per 128-node tile, 32 warps)
    {
        int smem = (2 * NDIM * NDIM + NWARPS * NPW * NDIM) * sizeof(float); // 192KB
        cudaFuncSetAttribute(node_kernel,
                             cudaFuncAttributeMaxDynamicSharedMemorySize, smem);
        int nodes_per_block = NWARPS * NPW; // 128
        int blocks = (n + nodes_per_block - 1) / nodes_per_block;
        node_kernel<<<blocks, 1024, smem>>>(W1, b1, W2, b2, gamma, beta, out, n);
    }
}

// round 17
// speedup vs baseline: 2.2289x; 1.2664x over previous
#include <cuda_runtime.h>
#include <cuda_bf16.h>

#define NDIM 128
#define EDIM 32
#define MAX_N 100000
#define MAX_NP 100096   // 782 full 128-row tiles

// h = (1+eps)*x (init) += scatter (edge). Padded rows stay zero forever.
__device__ float g_h[(size_t)MAX_NP * NDIM];

// ---------------- packed f32x2 helpers (edge kernel) ----------------
__device__ __forceinline__ unsigned long long pack2(float x, float y) {
    unsigned long long r;
    asm("mov.b64 %0, {%1, %2};" : "=l"(r) : "f"(x), "f"(y));
    return r;
}
__device__ __forceinline__ void unpack2(unsigned long long v, float& x, float& y) {
    asm("mov.b64 {%0, %1}, %2;" : "=f"(x), "=f"(y) : "l"(v));
}
__device__ __forceinline__ void ffma2(unsigned long long& d, unsigned long long a, unsigned long long b) {
    asm("fma.rn.f32x2 %0, %1, %2, %0;" : "+l"(d) : "l"(a), "l"(b));
}

// ---------------- kernel 1: h = (1+eps) * x ----------------
__global__ void init_h_kernel(const float* __restrict__ x,
                              const float* __restrict__ eps, int n) {
    float s = 1.0f + __ldg(eps);
    int total4 = n * (NDIM / 4);
    const float4* x4 = (const float4*)x;
    float4* h4 = (float4*)g_h;
    for (int i = blockIdx.x * blockDim.x + threadIdx.x; i < total4;
         i += gridDim.x * blockDim.x) {
        float4 v = x4[i];
        v.x *= s; v.y *= s; v.z *= s; v.w *= s;
        h4[i] = v;
    }
}

// ---------------- kernel 2: edge MLP + gather + scatter (R7 proven) ----------
#define EPW 8
__global__ __launch_bounds__(256) void edge_kernel(
    const float* __restrict__ x,
    const int* __restrict__ ei,
    const float* __restrict__ ea,
    const float* __restrict__ We,
    const float* __restrict__ be,
    int nE, int nN)
{
    __shared__ float sWe[EDIM * NDIM];
    __shared__ float sea[8][EPW][EDIM];

    int tid = threadIdx.x;
    for (int i = tid; i < EDIM * NDIM; i += blockDim.x) sWe[i] = We[i];

    int warp = tid >> 5, lane = tid & 31;
    int ebase = blockIdx.x * (8 * EPW) + warp * EPW;

    #pragma unroll
    for (int nn = 0; nn < EPW; nn++) {
        int e = ebase + nn;
        sea[warp][nn][lane] = (e < nE) ? __ldg(&ea[(size_t)e * EDIM + lane]) : 0.0f;
    }
    int iv = 0, jv = 0;
    if (lane < EPW) {
        int e = ebase + lane;
        if (e < nE) {
            iv = min(max(__ldg(&ei[e]), 0), nN - 1);
            jv = min(max(__ldg(&ei[nE + e]), 0), nN - 1);
        }
    }
    __syncthreads();

    unsigned long long acc[EPW][2];
    #pragma unroll
    for (int nn = 0; nn < EPW; nn++) { acc[nn][0] = 0ULL; acc[nn][1] = 0ULL; }

    const float4* We4 = (const float4*)sWe;
    #pragma unroll
    for (int dq = 0; dq < EDIM / 4; dq++) {
        float4 av[EPW];
        #pragma unroll
        for (int nn = 0; nn < EPW; nn++)
            av[nn] = ((const float4*)sea[warp][nn])[dq];
        #pragma unroll
        for (int k = 0; k < 4; k++) {
            int d = dq * 4 + k;
            float4 w = We4[d * 32 + lane];
            unsigned long long w01 = pack2(w.x, w.y);
            unsigned long long w23 = pack2(w.z, w.w);
            #pragma unroll
            for (int nn = 0; nn < EPW; nn++) {
                float a = (k == 0) ? av[nn].x : (k == 1) ? av[nn].y
                        : (k == 2) ? av[nn].z : av[nn].w;
                unsigned long long aa = pack2(a, a);
                ffma2(acc[nn][0], aa, w01);
                ffma2(acc[nn][1], aa, w23);
            }
        }
    }

    float4 b = __ldg(&((const float4*)be)[lane]);
    #pragma unroll
    for (int nn = 0; nn < EPW; nn++) {
        int e = ebase + nn;
        if (e < nE) {
            int jn  = __shfl_sync(0xffffffffu, jv, nn);
            int in_ = __shfl_sync(0xffffffffu, iv, nn);
            float4 xv = __ldg(&((const float4*)x)[(size_t)jn * 32 + lane]);
            float m0, m1, m2, m3;
            unpack2(acc[nn][0], m0, m1);
            unpack2(acc[nn][1], m2, m3);
            m0 += b.x + xv.x;
            m1 += b.y + xv.y;
            m2 += b.z + xv.z;
            m3 += b.w + xv.w;
            float* dst = g_h + (size_t)in_ * NDIM + lane * 4;
            asm volatile("red.global.add.v4.f32 [%0], {%1,%2,%3,%4};"
                         :: "l"(dst), "f"(m0), "f"(m1), "f"(m2), "f"(m3)
                         : "memory");
        }
    }
}

// ---------------- kernel 3: node MLP + LN via mma.sync tf32 ----------------
// XOR-swizzled smem word index: conflict-free fragment access
__device__ __forceinline__ int SWA(int m, int k) {
    return m * 128 + (k ^ ((m & 7) << 2));
}
__device__ __forceinline__ unsigned cvt_tf32(float f) {
    unsigned u;
    asm("cvt.rna.tf32.f32 %0, %1;" : "=r"(u) : "f"(f));
    return u;
}
__device__ __forceinline__ void mma_tf32(float* d, const unsigned* a,
                                         unsigned b0, unsigned b1) {
    asm volatile(
        "mma.sync.aligned.m16n8k8.row.col.f32.tf32.tf32.f32 "
        "{%0,%1,%2,%3}, {%4,%5,%6,%7}, {%8,%9}, {%0,%1,%2,%3};"
        : "+f"(d[0]), "+f"(d[1]), "+f"(d[2]), "+f"(d[3])
        : "r"(a[0]), "r"(a[1]), "r"(a[2]), "r"(a[3]), "r"(b0), "r"(b1));
}

// One GEMM layer: acc[2][8][4] += A(128x128) @ W(128x128), warp tile 32x64.
__device__ __forceinline__ void hmma_layer(float acc[2][8][4],
                                           const unsigned* sAu, const unsigned* sWu,
                                           int mrow, int ncol, int g, int t) {
    #pragma unroll 2
    for (int kt = 0; kt < 16; kt++) {
        int k0 = kt * 8 + t, k1 = k0 + 4;
        unsigned af[2][4];
        #pragma unroll
        for (int mt = 0; mt < 2; mt++) {
            int ra = mrow + mt * 16 + g, rb = ra + 8;
            af[mt][0] = sAu[SWA(ra, k0)];
            af[mt][1] = sAu[SWA(rb, k0)];
            af[mt][2] = sAu[SWA(ra, k1)];
            af[mt][3] = sAu[SWA(rb, k1)];
        }
        #pragma unroll
        for (int nt = 0; nt < 8; nt++) {
            int nn = ncol + nt * 8 + g;
            unsigned b0 = sWu[SWA(nn, k0)];
            unsigned b1 = sWu[SWA(nn, k1)];
            mma_tf32(acc[0][nt], af[0], b0, b1);
            mma_tf32(acc[1][nt], af[1], b0, b1);
        }
    }
}

__global__ __launch_bounds__(256) void node_hmma_kernel(
    const float* __restrict__ W1, const float* __restrict__ b1,
    const float* __restrict__ W2, const float* __restrict__ b2,
    const float* __restrict__ gamma, const float* __restrict__ beta,
    float* __restrict__ out, int n, int ntiles)
{
    extern __shared__ float sm[];
    float* sA    = sm;              // 16384 words, swizzled [m][k]
    float* sW1t  = sm + 16384;      // Wt: [n][k], swizzled, tf32-rounded
    float* sW2t  = sm + 32768;
    float* sSum  = sm + 49152;      // [2][128]
    float* sSq   = sSum + 256;      // [2][128]
    float* sG    = sSq + 256;       // 128
    float* sBt   = sG + 128;        // 128
    unsigned* sAu  = (unsigned*)sA;
    unsigned* sW1u = (unsigned*)sW1t;
    unsigned* sW2u = (unsigned*)sW2t;

    int tid = threadIdx.x, warp = tid >> 5, lane = tid & 31;
    int g = lane >> 2, t = lane & 3;
    int mrow = (warp >> 1) * 32;    // warp's 32-row group
    int ncol = (warp & 1) * 64;     // warp's 64-col half

    // stage W1^T, W2^T (once; persistent kernel)
    for (int li = tid; li < 16384; li += 256) {
        int k = li >> 7, nn = li & 127;      // W row-major [k][n]
        sW1u[SWA(nn, k)] = cvt_tf32(__ldg(&W1[li]));
        sW2u[SWA(nn, k)] = cvt_tf32(__ldg(&W2[li]));
    }
    if (tid < 128) { sG[tid] = __ldg(&gamma[tid]); sBt[tid] = __ldg(&beta[tid]); }

    // per-thread bias fragments (cols this thread's acc touches)
    float b1f[8][2], b2f[8][2];
    #pragma unroll
    for (int nt = 0; nt < 8; nt++) {
        int c0 = ncol + nt * 8 + 2 * t;
        b1f[nt][0] = __ldg(&b1[c0]); b1f[nt][1] = __ldg(&b1[c0 + 1]);
        b2f[nt][0] = __ldg(&b2[c0]); b2f[nt][1] = __ldg(&b2[c0 + 1]);
    }
    __syncthreads();

    for (int tile = blockIdx.x; tile < ntiles; tile += gridDim.x) {
        size_t tbase = (size_t)tile * 128;

        // ---- stage A = h tile (tf32-rounded, swizzled) ----
        #pragma unroll 4
        for (int i = 0; i < 16; i++) {
            int li = i * 1024 + tid * 4;
            int m = li >> 7, c = li & 127;
            float4 v = *(const float4*)(g_h + tbase * NDIM + li);
            unsigned* p = &sAu[SWA(m, c)];
            p[0] = cvt_tf32(v.x); p[1] = cvt_tf32(v.y);
            p[2] = cvt_tf32(v.z); p[3] = cvt_tf32(v.w);
        }
        __syncthreads();

        // ---- layer 1 ----
        float acc[2][8][4];
        #pragma unroll
        for (int mt = 0; mt < 2; mt++)
            #pragma unroll
            for (int nt = 0; nt < 8; nt++)
                #pragma unroll
                for (int j = 0; j < 4; j++) acc[mt][nt][j] = 0.0f;
        hmma_layer(acc, sAu, sW1u, mrow, ncol, g, t);
        __syncthreads();   // all reads of sA complete

        // ---- relu(acc + b1) -> tf32 -> restage into sA ----
        #pragma unroll
        for (int mt = 0; mt < 2; mt++) {
            int ra = mrow + mt * 16 + g;
            #pragma unroll
            for (int nt = 0; nt < 8; nt++) {
                int c0 = ncol + nt * 8 + 2 * t;
                unsigned u0 = cvt_tf32(fmaxf(acc[mt][nt][0] + b1f[nt][0], 0.0f));
                unsigned u1 = cvt_tf32(fmaxf(acc[mt][nt][1] + b1f[nt][1], 0.0f));
                unsigned u2 = cvt_tf32(fmaxf(acc[mt][nt][2] + b1f[nt][0], 0.0f));
                unsigned u3 = cvt_tf32(fmaxf(acc[mt][nt][3] + b1f[nt][1], 0.0f));
                *(uint2*)&sAu[SWA(ra, c0)]     = make_uint2(u0, u1);
                *(uint2*)&sAu[SWA(ra + 8, c0)] = make_uint2(u2, u3);
            }
        }
        __syncthreads();

        // ---- layer 2 ----
        #pragma unroll
        for (int mt = 0; mt < 2; mt++)
            #pragma unroll
            for (int nt = 0; nt < 8; nt++)
                #pragma unroll
                for (int j = 0; j < 4; j++) acc[mt][nt][j] = 0.0f;
        hmma_layer(acc, sAu, sW2u, mrow, ncol, g, t);
        __syncthreads();   // reads done before overwrite

        // ---- store o = acc + b2 (raw f32) into sA ----
        #pragma unroll
        for (int mt = 0; mt < 2; mt++) {
            int ra = mrow + mt * 16 + g;
            #pragma unroll
            for (int nt = 0; nt < 8; nt++) {
                int c0 = ncol + nt * 8 + 2 * t;
                float v0 = acc[mt][nt][0] + b2f[nt][0];
                float v1 = acc[mt][nt][1] + b2f[nt][1];
                float v2 = acc[mt][nt][2] + b2f[nt][0];
                float v3 = acc[mt][nt][3] + b2f[nt][1];
                *(float2*)&sA[SWA(ra, c0)]     = make_float2(v0, v1);
                *(float2*)&sA[SWA(ra + 8, c0)] = make_float2(v2, v3);
            }
        }
        __syncthreads();

        // ---- LayerNorm: 2 threads per row ----
        int r = tid >> 1, hf = tid & 1, cb = hf * 64;
        float s = 0.0f, s2 = 0.0f;
        #pragma unroll 4
        for (int q = 0; q < 16; q++) {
            float4 v = *(const float4*)&sA[SWA(r, cb + 4 * q)];
            s  += v.x + v.y + v.z + v.w;
            s2 += v.x * v.x + v.y * v.y + v.z * v.z + v.w * v.w;
        }
        sSum[hf * 128 + r] = s;
        sSq[hf * 128 + r]  = s2;
        __syncthreads();
        float ts  = sSum[r] + sSum[128 + r];
        float ts2 = sSq[r]  + sSq[128 + r];
        float mean = ts * (1.0f / NDIM);
        float var  = ts2 * (1.0f / NDIM) - mean * mean;
        float rstd = rsqrtf(var + 1e-5f);
        #pragma unroll 4
        for (int q = 0; q < 16; q++) {
            int c = cb + 4 * q;
            float4 v = *(const float4*)&sA[SWA(r, c)];
            v.x = (v.x - mean) * rstd * sG[c]     + sBt[c];
            v.y = (v.y - mean) * rstd * sG[c + 1] + sBt[c + 1];
            v.z = (v.z - mean) * rstd * sG[c + 2] + sBt[c + 2];
            v.w = (v.w - mean) * rstd * sG[c + 3] + sBt[c + 3];
            *(float4*)&sA[SWA(r, c)] = v;
        }
        __syncthreads();

        // ---- coalesced copy smem -> out ----
        #pragma unroll 4
        for (int i = 0; i < 16; i++) {
            int li = i * 1024 + tid * 4;
            int m = li >> 7, c = li & 127;
            if ((long)(tbase + m) < n) {
                float4 v = *(const float4*)&sA[SWA(m, c)];
                *(float4*)(out + tbase * NDIM + li) = v;
            }
        }
        __syncthreads();   // before next tile overwrites sA
    }
}

// ---------------- launch ----------------
extern "C" void kernel_launch(void* const* d_in, const int* in_sizes, int n_in,
                              void* d_out, int out_size) {
    const float* x      = (const float*)d_in[0];
    const int*   ei     = (const int*)d_in[1];     // int32
    const float* ea     = (const float*)d_in[2];
    const float* We     = (const float*)d_in[3];
    const float* be     = (const float*)d_in[4];
    const float* W1     = (const float*)d_in[5];
    const float* b1     = (const float*)d_in[6];
    const float* W2     = (const float*)d_in[7];
    const float* b2     = (const float*)d_in[8];
    const float* eps    = (const float*)d_in[9];
    const float* gamma  = (const float*)d_in[10];
    const float* beta   = (const float*)d_in[11];
    float* out = (float*)d_out;

    int n = in_sizes[0] / NDIM;        // 100000
    int nE = in_sizes[2] / EDIM;       // 600000

    // kernel 1: init h = (1+eps)*x
    {
        int total4 = n * (NDIM / 4);
        int blocks = (total4 + 255) / 256;
        if (blocks > 4096) blocks = 4096;
        init_h_kernel<<<blocks, 256>>>(x, eps, n);
    }
    // kernel 2: edges
    {
        int edges_per_block = 8 * EPW;  // 64
        int blocks = (nE + edges_per_block - 1) / edges_per_block;
        edge_kernel<<<blocks, 256>>>(x, ei, ea, We, be, nE, n);
    }
    // kernel 3: persistent tensor-core (mma.sync tf32) node MLP + LN
    {
        int sms = 148;
        cudaDeviceGetAttribute(&sms, cudaDevAttrMultiProcessorCount, 0);
        int smem = 49920 * sizeof(float);   // 199680 B
        cudaFuncSetAttribute(node_hmma_kernel,
                             cudaFuncAttributeMaxDynamicSharedMemorySize, smem);
        int ntiles = (n + 127) / 128;       // 782
        int blocks = (ntiles < sms) ? ntiles : sms;
        node_hmma_kernel<<<blocks, 256, smem>>>(W1, b1, W2, b2, gamma, beta,
                                                out, n, ntiles);
    }
}